// round 14
// baseline (speedup 1.0000x reference)
#include <cuda_runtime.h>

// PatchExtractor: crop(center square of bbox) + bilinear 224x224 + CLIP norm.
// R13: R6 body (proven best: 4 rows/thread, 12-load granule, occ ~83%)
// + persistent grid-stride launch (exactly one wave, no wave transitions).
//
// img    : [3, 2048, 2048] fp32
// bboxes : [N, 4] int32 (xyxy)
// out    : [N, 3, 224, 224] fp32

#define SIZE 224
#define ROWS_PER_THREAD 4
#define ROW_TILES (SIZE / ROWS_PER_THREAD)   // 56 row-tiles per patch
#define IMG_W 2048
#define IMG_H 2048
#define PLANE (IMG_H * IMG_W)
#define OUT_PLANE (SIZE * SIZE)
#define MAX_N 1024

// One full wave: 148 SMs x 9 resident blocks (224 thr, <=32 regs) = 1332
#define PERSISTENT_BLOCKS 1332

#define MEAN_R 0.48145466f
#define MEAN_G 0.4578275f
#define MEAN_B 0.40821073f
#define STD_R  0.26862954f
#define STD_G  0.26130258f
#define STD_B  0.27577711f

// Per-patch geometry: {ax, ay, step, unused};  sx = ax + x*step
__device__ float4 g_geom[MAX_N];

__global__ void geom_kernel(const int* __restrict__ bboxes, int N)
{
    int n = blockIdx.x * blockDim.x + threadIdx.x;
    if (n >= N) return;
    const float x0 = (float)bboxes[4 * n + 0];
    const float y0 = (float)bboxes[4 * n + 1];
    const float x1 = (float)bboxes[4 * n + 2];
    const float y1 = (float)bboxes[4 * n + 3];
    const float side = fminf(x1 - x0, y1 - y0);
    const float step = side * (1.0f / (float)SIZE);
    const float ax = 0.5f * (x0 + x1) - 0.5f * side + 0.5f * step - 0.5f;
    const float ay = 0.5f * (y0 + y1) - 0.5f * side + 0.5f * step - 0.5f;
    g_geom[n] = make_float4(ax, ay, step, 0.0f);
}

__global__ __launch_bounds__(SIZE, 8)
void patch_extract_kernel(const float* __restrict__ img,
                          float* __restrict__ out,
                          int num_units)
{
    const int x = threadIdx.x;          // output col

    const float* __restrict__ p0 = img;
    const float* __restrict__ p1 = img + PLANE;
    const float* __restrict__ p2 = img + 2 * PLANE;

    const float sR = 1.0f / (255.0f * STD_R), cR = MEAN_R / STD_R;
    const float sG = 1.0f / (255.0f * STD_G), cG = MEAN_G / STD_G;
    const float sB = 1.0f / (255.0f * STD_B), cB = MEAN_B / STD_B;

    // Persistent loop over (row-tile, patch) work units
    for (int u = blockIdx.x; u < num_units; u += PERSISTENT_BLOCKS) {
        const int t  = u % ROW_TILES;           // row-tile within patch
        const int n  = u / ROW_TILES;           // patch
        const int y0 = t * ROWS_PER_THREAD;

        const float4 g = g_geom[n];

        // x-geometry (upper clamp provably dead: sx <= 2046.5)
        float sx = fmaf((float)x, g.z, g.x);
        sx = fmaxf(sx, 0.0f);
        const int   ix0 = (int)sx;
        const float fx  = sx - (float)ix0;
        const float ex  = 1.0f - fx;

        float* __restrict__ dst = out + (n * 3 * OUT_PLANE + y0 * SIZE + x);

        #pragma unroll
        for (int k = 0; k < ROWS_PER_THREAD; ++k) {
            // per-row y-geometry, computed directly (no accumulation error)
            float sy = fmaf((float)(y0 + k), g.z, g.y);
            sy = fmaxf(sy, 0.0f);               // upper clamp dead (sy <= 2046)
            const int   iy = (int)sy;
            const float fy = sy - (float)iy;

            const int a = (iy << 11) + ix0;     // row iy; iy+1 <= 2047 ok
            const int b = a + IMG_W;

            const float r00 = __ldg(p0 + a), r01 = __ldg(p0 + a + 1);
            const float r10 = __ldg(p0 + b), r11 = __ldg(p0 + b + 1);
            const float g00 = __ldg(p1 + a), g01 = __ldg(p1 + a + 1);
            const float g10 = __ldg(p1 + b), g11 = __ldg(p1 + b + 1);
            const float b00 = __ldg(p2 + a), b01 = __ldg(p2 + a + 1);
            const float b10 = __ldg(p2 + b), b11 = __ldg(p2 + b + 1);

            const float ey  = 1.0f - fy;
            const float w00 = ex * ey, w01 = fx * ey;
            const float w10 = ex * fy, w11 = fx * fy;

            float vR = r00 * w00; vR = fmaf(r01, w01, vR);
            vR = fmaf(r10, w10, vR); vR = fmaf(r11, w11, vR);
            float vG = g00 * w00; vG = fmaf(g01, w01, vG);
            vG = fmaf(g10, w10, vG); vG = fmaf(g11, w11, vG);
            float vB = b00 * w00; vB = fmaf(b01, w01, vB);
            vB = fmaf(b10, w10, vB); vB = fmaf(b11, w11, vB);

            dst[k * SIZE]                 = fmaf(vR, sR, -cR);
            dst[k * SIZE + OUT_PLANE]     = fmaf(vG, sG, -cG);
            dst[k * SIZE + 2 * OUT_PLANE] = fmaf(vB, sB, -cB);
        }
    }
}

extern "C" void kernel_launch(void* const* d_in, const int* in_sizes, int n_in,
                              void* d_out, int out_size)
{
    const float* img    = (const float*)d_in[0];
    const int*   bboxes = (const int*)d_in[3];
    float* out = (float*)d_out;

    const int N = in_sizes[3] / 4;
    const int num_units = N * ROW_TILES;

    geom_kernel<<<(N + 255) / 256, 256>>>(bboxes, N);

    patch_extract_kernel<<<PERSISTENT_BLOCKS, SIZE>>>(img, out, num_units);
}

// round 16
// speedup vs baseline: 1.1881x; 1.1881x over previous
#include <cuda_runtime.h>

// PatchExtractor: crop(center square of bbox) + bilinear 224x224 + CLIP norm.
// R14: R6 proven body (4 rows/thread, 12-load granule, occ ~83%) with the
// geometry prepass inlined — single kernel, no serial geom launch in the graph.
//
// img    : [3, 2048, 2048] fp32
// bboxes : [N, 4] int32 (xyxy)
// out    : [N, 3, 224, 224] fp32

#define SIZE 224
#define ROWS_PER_THREAD 4
#define IMG_W 2048
#define IMG_H 2048
#define PLANE (IMG_H * IMG_W)
#define OUT_PLANE (SIZE * SIZE)

#define MEAN_R 0.48145466f
#define MEAN_G 0.4578275f
#define MEAN_B 0.40821073f
#define STD_R  0.26862954f
#define STD_G  0.26130258f
#define STD_B  0.27577711f

__global__ __launch_bounds__(SIZE, 8)
void patch_extract_kernel(const float* __restrict__ img,
                          const int4* __restrict__ bboxes,
                          float* __restrict__ out)
{
    const int y0 = blockIdx.x * ROWS_PER_THREAD;  // first output row
    const int n  = blockIdx.y;                    // patch
    const int x  = threadIdx.x;                   // output col

    // ---- inline per-patch geometry (uniform across block; ~12 ops) ----
    const int4 bb = __ldg(bboxes + n);
    const float bx0 = (float)bb.x, by0 = (float)bb.y;
    const float bx1 = (float)bb.z, by1 = (float)bb.w;
    const float side = fminf(bx1 - bx0, by1 - by0);
    const float step = side * (1.0f / (float)SIZE);
    // sx = ax + x*step
    const float ax = 0.5f * (bx0 + bx1) - 0.5f * side + 0.5f * step - 0.5f;
    const float ay = 0.5f * (by0 + by1) - 0.5f * side + 0.5f * step - 0.5f;

    // ---- shared x-geometry (all 4 rows). Upper clamp provably dead. ----
    float sx = fmaf((float)x, step, ax);
    sx = fmaxf(sx, 0.0f);
    const int   ix0 = (int)sx;
    const float fx  = sx - (float)ix0;
    const float ex  = 1.0f - fx;

    const float* __restrict__ p0 = img;
    const float* __restrict__ p1 = img + PLANE;
    const float* __restrict__ p2 = img + 2 * PLANE;

    const float sR = 1.0f / (255.0f * STD_R), cR = MEAN_R / STD_R;
    const float sG = 1.0f / (255.0f * STD_G), cG = MEAN_G / STD_G;
    const float sB = 1.0f / (255.0f * STD_B), cB = MEAN_B / STD_B;

    float* __restrict__ dst = out + (n * 3 * OUT_PLANE + y0 * SIZE + x);

    #pragma unroll
    for (int k = 0; k < ROWS_PER_THREAD; ++k) {
        float sy = fmaf((float)(y0 + k), step, ay);
        sy = fmaxf(sy, 0.0f);                 // upper clamp dead (sy <= 2046)
        const int   iy = (int)sy;
        const float fy = sy - (float)iy;

        const int a = (iy << 11) + ix0;       // row iy;   iy+1 <= 2047 ok
        const int b = a + IMG_W;              // row iy+1

        // 12-load batch (proven-good MLP granule at high occupancy)
        const float r00 = __ldg(p0 + a), r01 = __ldg(p0 + a + 1);
        const float r10 = __ldg(p0 + b), r11 = __ldg(p0 + b + 1);
        const float g00 = __ldg(p1 + a), g01 = __ldg(p1 + a + 1);
        const float g10 = __ldg(p1 + b), g11 = __ldg(p1 + b + 1);
        const float b00 = __ldg(p2 + a), b01 = __ldg(p2 + a + 1);
        const float b10 = __ldg(p2 + b), b11 = __ldg(p2 + b + 1);

        const float ey  = 1.0f - fy;
        const float w00 = ex * ey, w01 = fx * ey;
        const float w10 = ex * fy, w11 = fx * fy;

        float vR = r00 * w00; vR = fmaf(r01, w01, vR);
        vR = fmaf(r10, w10, vR); vR = fmaf(r11, w11, vR);
        float vG = g00 * w00; vG = fmaf(g01, w01, vG);
        vG = fmaf(g10, w10, vG); vG = fmaf(g11, w11, vG);
        float vB = b00 * w00; vB = fmaf(b01, w01, vB);
        vB = fmaf(b10, w10, vB); vB = fmaf(b11, w11, vB);

        dst[k * SIZE]                 = fmaf(vR, sR, -cR);
        dst[k * SIZE + OUT_PLANE]     = fmaf(vG, sG, -cG);
        dst[k * SIZE + 2 * OUT_PLANE] = fmaf(vB, sB, -cB);
    }
}

extern "C" void kernel_launch(void* const* d_in, const int* in_sizes, int n_in,
                              void* d_out, int out_size)
{
    const float* img    = (const float*)d_in[0];
    const int4*  bboxes = (const int4*)d_in[3];
    float* out = (float*)d_out;

    const int N = in_sizes[3] / 4;

    dim3 grid(SIZE / ROWS_PER_THREAD, N, 1);
    dim3 block(SIZE, 1, 1);
    patch_extract_kernel<<<grid, block>>>(img, bboxes, out);
}

// round 17
// speedup vs baseline: 1.2298x; 1.0351x over previous
#include <cuda_runtime.h>

// PatchExtractor: crop(center square of bbox) + bilinear 224x224 + CLIP norm.
// R16: R14 winner body (4 rows/thread, 12-load granule, inline geometry,
// occ ~83%) + max-L1 carveout + streaming stores (keep 154MB of write-once
// output from evicting the L2-resident image).
//
// img    : [3, 2048, 2048] fp32
// bboxes : [N, 4] int32 (xyxy)
// out    : [N, 3, 224, 224] fp32

#define SIZE 224
#define ROWS_PER_THREAD 4
#define IMG_W 2048
#define IMG_H 2048
#define PLANE (IMG_H * IMG_W)
#define OUT_PLANE (SIZE * SIZE)

#define MEAN_R 0.48145466f
#define MEAN_G 0.4578275f
#define MEAN_B 0.40821073f
#define STD_R  0.26862954f
#define STD_G  0.26130258f
#define STD_B  0.27577711f

__global__ __launch_bounds__(SIZE, 8)
void patch_extract_kernel(const float* __restrict__ img,
                          const int4* __restrict__ bboxes,
                          float* __restrict__ out)
{
    const int y0 = blockIdx.x * ROWS_PER_THREAD;  // first output row
    const int n  = blockIdx.y;                    // patch
    const int x  = threadIdx.x;                   // output col

    // ---- inline per-patch geometry (uniform across block; ~12 ops) ----
    const int4 bb = __ldg(bboxes + n);
    const float bx0 = (float)bb.x, by0 = (float)bb.y;
    const float bx1 = (float)bb.z, by1 = (float)bb.w;
    const float side = fminf(bx1 - bx0, by1 - by0);
    const float step = side * (1.0f / (float)SIZE);
    const float ax = 0.5f * (bx0 + bx1) - 0.5f * side + 0.5f * step - 0.5f;
    const float ay = 0.5f * (by0 + by1) - 0.5f * side + 0.5f * step - 0.5f;

    // ---- shared x-geometry (all 4 rows). Upper clamp provably dead. ----
    float sx = fmaf((float)x, step, ax);
    sx = fmaxf(sx, 0.0f);
    const int   ix0 = (int)sx;
    const float fx  = sx - (float)ix0;
    const float ex  = 1.0f - fx;

    const float* __restrict__ p0 = img;
    const float* __restrict__ p1 = img + PLANE;
    const float* __restrict__ p2 = img + 2 * PLANE;

    const float sR = 1.0f / (255.0f * STD_R), cR = MEAN_R / STD_R;
    const float sG = 1.0f / (255.0f * STD_G), cG = MEAN_G / STD_G;
    const float sB = 1.0f / (255.0f * STD_B), cB = MEAN_B / STD_B;

    float* __restrict__ dst = out + (n * 3 * OUT_PLANE + y0 * SIZE + x);

    #pragma unroll
    for (int k = 0; k < ROWS_PER_THREAD; ++k) {
        float sy = fmaf((float)(y0 + k), step, ay);
        sy = fmaxf(sy, 0.0f);                 // upper clamp dead (sy <= 2046)
        const int   iy = (int)sy;
        const float fy = sy - (float)iy;

        const int a = (iy << 11) + ix0;       // row iy;   iy+1 <= 2047 ok
        const int b = a + IMG_W;              // row iy+1

        // 12-load batch (proven-good MLP granule at high occupancy)
        const float r00 = __ldg(p0 + a), r01 = __ldg(p0 + a + 1);
        const float r10 = __ldg(p0 + b), r11 = __ldg(p0 + b + 1);
        const float g00 = __ldg(p1 + a), g01 = __ldg(p1 + a + 1);
        const float g10 = __ldg(p1 + b), g11 = __ldg(p1 + b + 1);
        const float b00 = __ldg(p2 + a), b01 = __ldg(p2 + a + 1);
        const float b10 = __ldg(p2 + b), b11 = __ldg(p2 + b + 1);

        const float ey  = 1.0f - fy;
        const float w00 = ex * ey, w01 = fx * ey;
        const float w10 = ex * fy, w11 = fx * fy;

        float vR = r00 * w00; vR = fmaf(r01, w01, vR);
        vR = fmaf(r10, w10, vR); vR = fmaf(r11, w11, vR);
        float vG = g00 * w00; vG = fmaf(g01, w01, vG);
        vG = fmaf(g10, w10, vG); vG = fmaf(g11, w11, vG);
        float vB = b00 * w00; vB = fmaf(b01, w01, vB);
        vB = fmaf(b10, w10, vB); vB = fmaf(b11, w11, vB);

        // Streaming stores: output is write-once; don't evict image from L2.
        __stwt(dst + k * SIZE,                 fmaf(vR, sR, -cR));
        __stwt(dst + k * SIZE + OUT_PLANE,     fmaf(vG, sG, -cG));
        __stwt(dst + k * SIZE + 2 * OUT_PLANE, fmaf(vB, sB, -cB));
    }
}

extern "C" void kernel_launch(void* const* d_in, const int* in_sizes, int n_in,
                              void* d_out, int out_size)
{
    const float* img    = (const float*)d_in[0];
    const int4*  bboxes = (const int4*)d_in[3];
    float* out = (float*)d_out;

    const int N = in_sizes[3] / 4;

    // No smem used: give the full unified carveout to L1 data cache so the
    // gather working set stays resident. Idempotent; safe under capture.
    cudaFuncSetAttribute(patch_extract_kernel,
                         cudaFuncAttributePreferredSharedMemoryCarveout, 0);

    dim3 grid(SIZE / ROWS_PER_THREAD, N, 1);
    dim3 block(SIZE, 1, 1);
    patch_extract_kernel<<<grid, block>>>(img, bboxes, out);
}